// round 5
// baseline (speedup 1.0000x reference)
#include <cuda_runtime.h>
#include <cstdint>

#define NN 100000
#define EE 1600000
#define DD 128
#define HH 128

// Single-relation scratch (51.2 MB): stays L2-resident together with x (51.2 MB).
__device__ float4 g_s4[NN][DD / 4];
__device__ float  g_deg[NN];

// ---------------------------------------------------------------------------
// Zero scratch (s + deg in one kernel)
// ---------------------------------------------------------------------------
__global__ void zero_kernel() {
    int i = blockIdx.x * blockDim.x + threadIdx.x;
    int total4 = NN * (DD / 4);                  // 3.2M float4
    if (i < total4) ((float4*)g_s4)[i] = make_float4(0.f, 0.f, 0.f, 0.f);
    if (i < NN) g_deg[i] = 0.f;
}

// ---------------------------------------------------------------------------
// Edge scatter for ONE relation: warp per edge. Gather x[src] (32 lanes x
// float4 = 512B), scale by w, f32x4 atomicAdd into s[dst] (L2-resident).
// ---------------------------------------------------------------------------
__global__ void edge_kernel(
    const float* __restrict__ x,
    const int* __restrict__ src, const int* __restrict__ dst,
    const float* __restrict__ w)
{
    int e = (int)((blockIdx.x * blockDim.x + threadIdx.x) >> 5);
    if (e >= EE) return;
    int lane = threadIdx.x & 31;

    int   u  = __ldg(&src[e]);
    int   v  = __ldg(&dst[e]);
    float ww = __ldg(&w[e]);

    float4 xv = ((const float4*)x)[(size_t)u * 32 + lane];
    float4 m  = make_float4(xv.x * ww, xv.y * ww, xv.z * ww, xv.w * ww);

    atomicAdd(&g_s4[v][lane], m);                 // RED.E.ADD.F32x4

    if (lane == 0) atomicAdd(&g_deg[v], 1.0f);
}

// ---------------------------------------------------------------------------
// Packed f32x2 helpers
// ---------------------------------------------------------------------------
__device__ __forceinline__ uint64_t fma2(uint64_t a, uint64_t b, uint64_t c) {
    uint64_t d;
    asm("fma.rn.f32x2 %0, %1, %2, %3;" : "=l"(d) : "l"(a), "l"(b), "l"(c));
    return d;
}
__device__ __forceinline__ void unpack2(uint64_t d, float& lo, float& hi) {
    asm("mov.b64 {%0, %1}, %2;" : "=f"(lo), "=f"(hi) : "l"(d));
}

// B-tile swizzle: pad 4 floats every 32 -> 16 tx-groups hit each bank pair
// exactly twice (optimal 2-phase for a 512B warp read).
#define BCOL(c) ((c) + (((c) >> 5) << 2))
#define BROW 144   // 128 + 4*4 pad, 16B-aligned row stride (144*4=576B)

// ---------------------------------------------------------------------------
// GEMM for ONE relation:
//   z = [x | s*invdeg] @ [Wself ; Wneigh] + b      (K=256)
//   out (+)= relu(z) / 3
// Block 128x128, 256 threads, 8x8/thread.
// A stored DUPLICATED in shared ({a,a} pairs are direct LDS, broadcast);
// B pairs {b2j,b2j+1} natural from contiguous Bs. Zero-MOV FFMA2 mainloop.
// ---------------------------------------------------------------------------
__global__ __launch_bounds__(256, 2) void gemm_kernel(
    const float* __restrict__ x,
    const float* __restrict__ Ws, const float* __restrict__ Wn,
    const float* __restrict__ b,
    float* __restrict__ out, int first)
{
    __shared__ __align__(16) float As[16][264];   // duplicated: [kk][2*row(+0/1)]
    __shared__ __align__(16) float Bs[16][BROW];  // swizzled cols
    __shared__ float sdeg[128];

    int t  = threadIdx.x;
    int m0 = blockIdx.x * 128;

    if (t < 128) {
        int m = m0 + t;
        sdeg[t] = (m < NN) ? (1.0f / fmaxf(g_deg[m], 1.0f)) : 0.0f;
    }
    __syncthreads();

    int tx = t & 15;    // col group: cols tx*8 .. tx*8+7
    int ty = t >> 4;    // row group: rows ty*8 .. ty*8+7

    uint64_t z[8][4];   // [row i][col pair j] = {out(i,2j), out(i,2j+1)}
    #pragma unroll
    for (int i = 0; i < 8; i++)
        #pragma unroll
        for (int j = 0; j < 4; j++) z[i][j] = 0ull;

    const float* srBase = (const float*)&g_s4[0][0];

    for (int kt = 0; kt < 16; kt++) {
        // ---- load A tile (transposed + duplicated): 128 rows x 16 k
        #pragma unroll
        for (int h = 0; h < 2; h++) {
            int f   = t + h * 256;
            int row = f >> 2;
            int kq  = f & 3;
            int k   = kt * 16 + kq * 4;
            int m   = m0 + row;
            float4 v = make_float4(0.f, 0.f, 0.f, 0.f);
            if (m < NN) {
                if (k < 128) {
                    v = *(const float4*)(x + (size_t)m * 128 + k);
                } else {
                    v = *(const float4*)(srBase + (size_t)m * 128 + (k - 128));
                    float iv = sdeg[row];
                    v.x *= iv; v.y *= iv; v.z *= iv; v.w *= iv;
                }
            }
            int r2 = row * 2;
            As[kq * 4 + 0][r2] = v.x;  As[kq * 4 + 0][r2 + 1] = v.x;
            As[kq * 4 + 1][r2] = v.y;  As[kq * 4 + 1][r2 + 1] = v.y;
            As[kq * 4 + 2][r2] = v.z;  As[kq * 4 + 2][r2 + 1] = v.z;
            As[kq * 4 + 3][r2] = v.w;  As[kq * 4 + 3][r2 + 1] = v.w;
        }
        // ---- load B tile: 16 k x 128 cols (swizzled)
        #pragma unroll
        for (int h = 0; h < 2; h++) {
            int f  = t + h * 256;
            int kk = f >> 5;
            int cq = f & 31;
            int k  = kt * 16 + kk;
            float4 v;
            if (k < 128) v = *(const float4*)(Ws + (size_t)k * 128 + cq * 4);
            else         v = *(const float4*)(Wn + (size_t)(k - 128) * 128 + cq * 4);
            *(float4*)&Bs[kk][BCOL(cq * 4)] = v;
        }
        __syncthreads();

        #pragma unroll
        for (int kk = 0; kk < 16; kk++) {
            // a-pairs {a_i,a_i}: 64B contiguous, address depends only on ty
            // -> LDS.128 broadcasts, conflict-free.
            uint64_t a2[8];
            {
                const uint4* ap = (const uint4*)&As[kk][ty * 16];
                uint4 q0 = ap[0], q1 = ap[1], q2 = ap[2], q3 = ap[3];
                a2[0] = (uint64_t)q0.x | ((uint64_t)q0.y << 32);
                a2[1] = (uint64_t)q0.z | ((uint64_t)q0.w << 32);
                a2[2] = (uint64_t)q1.x | ((uint64_t)q1.y << 32);
                a2[3] = (uint64_t)q1.z | ((uint64_t)q1.w << 32);
                a2[4] = (uint64_t)q2.x | ((uint64_t)q2.y << 32);
                a2[5] = (uint64_t)q2.z | ((uint64_t)q2.w << 32);
                a2[6] = (uint64_t)q3.x | ((uint64_t)q3.y << 32);
                a2[7] = (uint64_t)q3.z | ((uint64_t)q3.w << 32);
            }
            // b-pairs {b_2j, b_2j+1}: natural contiguous pairs (32B)
            uint64_t bp[4];
            {
                const uint4* bq = (const uint4*)&Bs[kk][BCOL(tx * 8)];
                uint4 q0 = bq[0], q1 = bq[1];
                bp[0] = (uint64_t)q0.x | ((uint64_t)q0.y << 32);
                bp[1] = (uint64_t)q0.z | ((uint64_t)q0.w << 32);
                bp[2] = (uint64_t)q1.x | ((uint64_t)q1.y << 32);
                bp[3] = (uint64_t)q1.z | ((uint64_t)q1.w << 32);
            }
            #pragma unroll
            for (int i = 0; i < 8; i++)
                #pragma unroll
                for (int j = 0; j < 4; j++)
                    z[i][j] = fma2(a2[i], bp[j], z[i][j]);
        }
        __syncthreads();
    }

    // ---- epilogue: bias + relu, scale 1/3, accumulate into out
    const float third = 1.0f / 3.0f;
    float bv[8];
    #pragma unroll
    for (int j = 0; j < 8; j++) bv[j] = __ldg(&b[tx * 8 + j]);

    #pragma unroll
    for (int i = 0; i < 8; i++) {
        int m = m0 + ty * 8 + i;
        if (m >= NN) continue;
        float* op = out + (size_t)m * 128 + tx * 8;
        float v[8];
        #pragma unroll
        for (int j2 = 0; j2 < 4; j2++) {
            float lo, hi;
            unpack2(z[i][j2], lo, hi);
            v[2 * j2 + 0] = fmaxf(lo + bv[2 * j2 + 0], 0.f) * third;
            v[2 * j2 + 1] = fmaxf(hi + bv[2 * j2 + 1], 0.f) * third;
        }
        if (!first) {
            float4 o0 = *(const float4*)(op);
            float4 o1 = *(const float4*)(op + 4);
            v[0] += o0.x; v[1] += o0.y; v[2] += o0.z; v[3] += o0.w;
            v[4] += o1.x; v[5] += o1.y; v[6] += o1.z; v[7] += o1.w;
        }
        *(float4*)(op)     = make_float4(v[0], v[1], v[2], v[3]);
        *(float4*)(op + 4) = make_float4(v[4], v[5], v[6], v[7]);
    }
}

// ---------------------------------------------------------------------------
// Launch. Inputs identified BY SIZE (robust to either metadata ordering).
// ---------------------------------------------------------------------------
extern "C" void kernel_launch(void* const* d_in, const int* in_sizes, int n_in,
                              void* d_out, int out_size)
{
    const float* x = nullptr;
    const int*   srcA[3] = {nullptr, nullptr, nullptr};
    const int*   dstA[3] = {nullptr, nullptr, nullptr};
    const float* wA[3]   = {nullptr, nullptr, nullptr};
    const float* WsA[3]  = {nullptr, nullptr, nullptr};
    const float* WnA[3]  = {nullptr, nullptr, nullptr};
    const float* bA[3]   = {nullptr, nullptr, nullptr};

    int nEdge = 0, nMat = 0, nBias = 0;
    for (int i = 0; i < n_in; i++) {
        int sz = in_sizes[i];
        if (sz == NN * DD) {
            x = (const float*)d_in[i];
        } else if (sz == EE) {
            int k = nEdge++;
            int rel = k / 3, kind = k % 3;
            if (rel < 3) {
                if (kind == 0)      srcA[rel] = (const int*)d_in[i];
                else if (kind == 1) dstA[rel] = (const int*)d_in[i];
                else                wA[rel]   = (const float*)d_in[i];
            }
        } else if (sz == DD * HH) {
            int k = nMat++;
            int rel = k / 2;
            if (rel < 3) {
                if ((k & 1) == 0) WsA[rel] = (const float*)d_in[i];
                else              WnA[rel] = (const float*)d_in[i];
            }
        } else if (sz == HH) {
            if (nBias < 3) bA[nBias++] = (const float*)d_in[i];
        }
    }

    float* out = (float*)d_out;

    int zeroBlocks = (NN * (DD / 4) + 255) / 256;
    int edgeBlocks = (EE + 7) / 8;
    int gemmBlocks = (NN + 127) / 128;

    for (int r = 0; r < 3; r++) {
        zero_kernel<<<zeroBlocks, 256>>>();
        edge_kernel<<<edgeBlocks, 256>>>(x, srcA[r], dstA[r], wA[r]);
        gemm_kernel<<<gemmBlocks, 256>>>(x, WsA[r], WnA[r], bA[r], out, r == 0);
    }
}

// round 7
// speedup vs baseline: 1.3157x; 1.3157x over previous
#include <cuda_runtime.h>
#include <cuda_bf16.h>
#include <cstdint>

#define NN 100000
#define EE 1600000
#define DD 128
#define HH 128

// ---------------------------------------------------------------------------
// Scratch
// ---------------------------------------------------------------------------
__device__ float4 g_s4[NN][DD / 4];          // neighbor sums (one relation)
__device__ float  g_deg[NN];
// B^T = [Ws;Wn]^T in [n][k] layout (128 x 256), bf16 hi/lo split.
__device__ __nv_bfloat16 g_Bhi[128 * 256];
__device__ __nv_bfloat16 g_Blo[128 * 256];

// ---------------------------------------------------------------------------
// Zero scratch
// ---------------------------------------------------------------------------
__global__ void zero_kernel() {
    int i = blockIdx.x * blockDim.x + threadIdx.x;
    int total4 = NN * (DD / 4);
    if (i < total4) ((float4*)g_s4)[i] = make_float4(0.f, 0.f, 0.f, 0.f);
    if (i < NN) g_deg[i] = 0.f;
}

// ---------------------------------------------------------------------------
// Edge scatter: warp per edge, f32x4 RED into L2-resident s
// ---------------------------------------------------------------------------
__global__ void edge_kernel(
    const float* __restrict__ x,
    const int* __restrict__ src, const int* __restrict__ dst,
    const float* __restrict__ w)
{
    int e = (int)((blockIdx.x * blockDim.x + threadIdx.x) >> 5);
    if (e >= EE) return;
    int lane = threadIdx.x & 31;

    int   u  = __ldg(&src[e]);
    int   v  = __ldg(&dst[e]);
    float ww = __ldg(&w[e]);

    float4 xv = ((const float4*)x)[(size_t)u * 32 + lane];
    float4 m  = make_float4(xv.x * ww, xv.y * ww, xv.z * ww, xv.w * ww);

    atomicAdd(&g_s4[v][lane], m);
    if (lane == 0) atomicAdd(&g_deg[v], 1.0f);
}

// ---------------------------------------------------------------------------
// B pre-convert: g_Bhi/g_Blo[n][k] = hi/lo(W[k][n]), W = [Ws;Wn]
// ---------------------------------------------------------------------------
__global__ void bconv_kernel(const float* __restrict__ Ws, const float* __restrict__ Wn) {
    int k = blockIdx.x;      // 0..255
    int n = threadIdx.x;     // 0..127
    float wv = (k < 128) ? __ldg(&Ws[k * 128 + n]) : __ldg(&Wn[(k - 128) * 128 + n]);
    __nv_bfloat16 h = __float2bfloat16(wv);
    __nv_bfloat16 l = __float2bfloat16(wv - __bfloat162float(h));
    g_Bhi[n * 256 + k] = h;
    g_Blo[n * 256 + k] = l;
}

// ---------------------------------------------------------------------------
// PTX helpers: ldmatrix + bf16 mma (baseline sm_80+ features, OK for sm_103)
// ---------------------------------------------------------------------------
__device__ __forceinline__ uint32_t smem_u32(const void* p) {
    uint32_t a;
    asm("{ .reg .u64 t; cvta.to.shared.u64 t, %1; cvt.u32.u64 %0, t; }"
        : "=r"(a) : "l"(p));
    return a;
}
#define LDSM_X4(r0, r1, r2, r3, addr) \
    asm volatile("ldmatrix.sync.aligned.m8n8.x4.shared.b16 {%0,%1,%2,%3}, [%4];" \
        : "=r"(r0), "=r"(r1), "=r"(r2), "=r"(r3) : "r"(addr))
#define LDSM_X2(r0, r1, addr) \
    asm volatile("ldmatrix.sync.aligned.m8n8.x2.shared.b16 {%0,%1}, [%2];" \
        : "=r"(r0), "=r"(r1) : "r"(addr))
#define MMA_BF16(d, a, b) \
    asm volatile("mma.sync.aligned.m16n8k16.row.col.f32.bf16.bf16.f32 " \
        "{%0,%1,%2,%3}, {%4,%5,%6,%7}, {%8,%9}, {%0,%1,%2,%3};" \
        : "+f"((d)[0]), "+f"((d)[1]), "+f"((d)[2]), "+f"((d)[3]) \
        : "r"((a)[0]), "r"((a)[1]), "r"((a)[2]), "r"((a)[3]), \
          "r"((b)[0]), "r"((b)[1]))

// smem row stride for bf16 tiles: 40 b16 = 80B (conflict-free ldmatrix phases)
#define ASTR 40

// ---------------------------------------------------------------------------
// Tensor-core GEMM (mma.sync bf16, 3-pass hi/lo split), one relation:
//   z = [x | s*invdeg] @ [Ws;Wn] + b ;  out (+)= relu(z)/3
// CTA 128x128, 8 warps (4M x 2N), warp tile 32x64. K chunks of 32.
// ---------------------------------------------------------------------------
__global__ __launch_bounds__(256, 2) void gemm_mma_kernel(
    const float* __restrict__ x, const float* __restrict__ bias,
    float* __restrict__ out, int first)
{
    __shared__ __align__(16) __nv_bfloat16 sAhi[128][ASTR];
    __shared__ __align__(16) __nv_bfloat16 sAlo[128][ASTR];
    __shared__ __align__(16) __nv_bfloat16 sBhi[128][ASTR];
    __shared__ __align__(16) __nv_bfloat16 sBlo[128][ASTR];
    __shared__ float sdeg[128];

    int tid = threadIdx.x;
    int wid = tid >> 5, lid = tid & 31;
    int m0  = blockIdx.x * 128;

    if (tid < 128) {
        int m = m0 + tid;
        sdeg[tid] = (m < NN) ? (1.0f / fmaxf(g_deg[m], 1.0f)) : 0.0f;
    }
    __syncthreads();

    int wm = wid & 3;        // M quadrant: rows wm*32 .. +31
    int wn = wid >> 2;       // N half:    cols wn*64 .. +63

    float acc[2][8][4];
    #pragma unroll
    for (int i = 0; i < 2; i++)
        #pragma unroll
        for (int j = 0; j < 8; j++)
            #pragma unroll
            for (int q = 0; q < 4; q++) acc[i][j][q] = 0.f;

    uint32_t aHiBase = smem_u32(&sAhi[0][0]);
    uint32_t aLoBase = smem_u32(&sAlo[0][0]);
    uint32_t bHiBase = smem_u32(&sBhi[0][0]);
    uint32_t bLoBase = smem_u32(&sBlo[0][0]);

    // ldmatrix lane addressing offsets (b16 units -> bytes at use site)
    int aRow = lid & 15;            // row within 16-row tile
    int aKof = (lid >> 4) * 8;      // k offset 0/8
    int bRow = lid & 7;             // n within 8-col tile
    int bKof = ((lid >> 3) & 1) * 8;

    for (int c = 0; c < 8; c++) {
        // ---- stage A chunk (128 rows x 32 k) as bf16 hi/lo
        #pragma unroll
        for (int h = 0; h < 4; h++) {
            int f   = tid + h * 256;      // 0..1023
            int row = f >> 3;
            int kq  = f & 7;              // float4 index within 32 k
            int m   = m0 + row;
            float4 v = make_float4(0.f, 0.f, 0.f, 0.f);
            if (m < NN) {
                if (c < 4) {
                    v = __ldg((const float4*)(x + (size_t)m * 128 + c * 32) + kq);
                } else {
                    v = __ldg((const float4*)&g_s4[m][0] + (c - 4) * 8 + kq);
                    float iv = sdeg[row];
                    v.x *= iv; v.y *= iv; v.z *= iv; v.w *= iv;
                }
            }
            __nv_bfloat16 h0 = __float2bfloat16(v.x), h1 = __float2bfloat16(v.y);
            __nv_bfloat16 h2 = __float2bfloat16(v.z), h3 = __float2bfloat16(v.w);
            __nv_bfloat16 l0 = __float2bfloat16(v.x - __bfloat162float(h0));
            __nv_bfloat16 l1 = __float2bfloat16(v.y - __bfloat162float(h1));
            __nv_bfloat16 l2 = __float2bfloat16(v.z - __bfloat162float(h2));
            __nv_bfloat16 l3 = __float2bfloat16(v.w - __bfloat162float(h3));
            uint32_t hp0 = (uint32_t)__bfloat16_as_ushort(h0) |
                           ((uint32_t)__bfloat16_as_ushort(h1) << 16);
            uint32_t hp1 = (uint32_t)__bfloat16_as_ushort(h2) |
                           ((uint32_t)__bfloat16_as_ushort(h3) << 16);
            uint32_t lp0 = (uint32_t)__bfloat16_as_ushort(l0) |
                           ((uint32_t)__bfloat16_as_ushort(l1) << 16);
            uint32_t lp1 = (uint32_t)__bfloat16_as_ushort(l2) |
                           ((uint32_t)__bfloat16_as_ushort(l3) << 16);
            *(uint2*)&sAhi[row][kq * 4] = make_uint2(hp0, hp1);
            *(uint2*)&sAlo[row][kq * 4] = make_uint2(lp0, lp1);
        }
        // ---- stage B chunk (128 n x 32 k) from pre-split global
        #pragma unroll
        for (int h = 0; h < 2; h++) {
            int f  = tid + h * 256;       // 0..511
            int n  = f >> 2;
            int kq = f & 3;               // float4 = 8 bf16
            const float4* sh = (const float4*)(g_Bhi + n * 256 + c * 32) + kq;
            const float4* sl = (const float4*)(g_Blo + n * 256 + c * 32) + kq;
            *(float4*)&sBhi[n][kq * 8] = __ldg(sh);
            *(float4*)&sBlo[n][kq * 8] = __ldg(sl);
        }
        __syncthreads();

        // ---- 2 k-steps of 16
        #pragma unroll
        for (int ks = 0; ks < 2; ks++) {
            uint32_t ahi[2][4], alo[2][4];
            #pragma unroll
            for (int mt = 0; mt < 2; mt++) {
                uint32_t off = (uint32_t)(((wm * 32 + mt * 16 + aRow) * ASTR
                                           + ks * 16 + aKof) * 2);
                LDSM_X4(ahi[mt][0], ahi[mt][1], ahi[mt][2], ahi[mt][3], aHiBase + off);
                LDSM_X4(alo[mt][0], alo[mt][1], alo[mt][2], alo[mt][3], aLoBase + off);
            }
            #pragma unroll
            for (int nt = 0; nt < 8; nt++) {
                uint32_t bo = (uint32_t)(((wn * 64 + nt * 8 + bRow) * ASTR
                                          + ks * 16 + bKof) * 2);
                uint32_t bhi[2], blo[2];
                LDSM_X2(bhi[0], bhi[1], bHiBase + bo);
                LDSM_X2(blo[0], blo[1], bLoBase + bo);
                #pragma unroll
                for (int mt = 0; mt < 2; mt++) {
                    MMA_BF16(acc[mt][nt], ahi[mt], bhi);
                    MMA_BF16(acc[mt][nt], alo[mt], bhi);
                    MMA_BF16(acc[mt][nt], ahi[mt], blo);
                }
            }
        }
        __syncthreads();
    }

    // ---- epilogue: bias + relu, scale 1/3, RMW out
    const float third = 1.0f / 3.0f;
    int tq = lid >> 2;       // row within 8
    int tr = lid & 3;        // col pair
    #pragma unroll
    for (int mt = 0; mt < 2; mt++) {
        int rbase = m0 + wm * 32 + mt * 16 + tq;
        #pragma unroll
        for (int hf = 0; hf < 2; hf++) {
            int row = rbase + hf * 8;
            if (row >= NN) continue;
            float* op = out + (size_t)row * 128;
            #pragma unroll
            for (int nt = 0; nt < 8; nt++) {
                int col = wn * 64 + nt * 8 + tr * 2;
                float v0 = acc[mt][nt][hf * 2 + 0] + __ldg(&bias[col]);
                float v1 = acc[mt][nt][hf * 2 + 1] + __ldg(&bias[col + 1]);
                v0 = fmaxf(v0, 0.f) * third;
                v1 = fmaxf(v1, 0.f) * third;
                if (!first) {
                    float2 o = *(const float2*)(op + col);
                    v0 += o.x; v1 += o.y;
                }
                *(float2*)(op + col) = make_float2(v0, v1);
            }
        }
    }
}

// ---------------------------------------------------------------------------
// Launch. Inputs identified BY SIZE (robust to either metadata ordering).
// ---------------------------------------------------------------------------
extern "C" void kernel_launch(void* const* d_in, const int* in_sizes, int n_in,
                              void* d_out, int out_size)
{
    const float* x = nullptr;
    const int*   srcA[3] = {nullptr, nullptr, nullptr};
    const int*   dstA[3] = {nullptr, nullptr, nullptr};
    const float* wA[3]   = {nullptr, nullptr, nullptr};
    const float* WsA[3]  = {nullptr, nullptr, nullptr};
    const float* WnA[3]  = {nullptr, nullptr, nullptr};
    const float* bA[3]   = {nullptr, nullptr, nullptr};

    int nEdge = 0, nMat = 0, nBias = 0;
    for (int i = 0; i < n_in; i++) {
        int sz = in_sizes[i];
        if (sz == NN * DD) {
            x = (const float*)d_in[i];
        } else if (sz == EE) {
            int k = nEdge++;
            int rel = k / 3, kind = k % 3;
            if (rel < 3) {
                if (kind == 0)      srcA[rel] = (const int*)d_in[i];
                else if (kind == 1) dstA[rel] = (const int*)d_in[i];
                else                wA[rel]   = (const float*)d_in[i];
            }
        } else if (sz == DD * HH) {
            int k = nMat++;
            int rel = k / 2;
            if (rel < 3) {
                if ((k & 1) == 0) WsA[rel] = (const float*)d_in[i];
                else              WnA[rel] = (const float*)d_in[i];
            }
        } else if (sz == HH) {
            if (nBias < 3) bA[nBias++] = (const float*)d_in[i];
        }
    }

    float* out = (float*)d_out;

    int zeroBlocks = (NN * (DD / 4) + 255) / 256;
    int edgeBlocks = (EE + 7) / 8;
    int gemmBlocks = (NN + 127) / 128;   // 782

    for (int r = 0; r < 3; r++) {
        zero_kernel<<<zeroBlocks, 256>>>();
        edge_kernel<<<edgeBlocks, 256>>>(x, srcA[r], dstA[r], wA[r]);
        bconv_kernel<<<256, 128>>>(WsA[r], WnA[r]);
        gemm_mma_kernel<<<gemmBlocks, 256>>>(x, bA[r], out, r == 0);
    }
}